// round 6
// baseline (speedup 1.0000x reference)
#include <cuda_runtime.h>
#include <cstdint>

#define BDIM   16384
#define FDIM   256
#define BOND   16
#define NFREQ  4
#define DIN0   (1 + 2*NFREQ)   // 9

__device__ float g_xT[FDIM * BDIM];
__device__ float g_bufA[128 * BDIM * BOND];
__device__ float g_bufB[64  * BDIM * BOND];

__device__ __forceinline__ unsigned long long ffma2(unsigned long long a,
                                                    unsigned long long b,
                                                    unsigned long long c) {
    unsigned long long d;
    asm("fma.rn.f32x2 %0, %1, %2, %3;" : "=l"(d) : "l"(a), "l"(b), "l"(c));
    return d;
}
__device__ __forceinline__ unsigned long long pack2(float x, float y) {
    unsigned long long r;
    asm("mov.b64 %0, {%1, %2};" : "=l"(r) : "f"(x), "f"(y));
    return r;
}
__device__ __forceinline__ float2 unpack2(unsigned long long v) {
    float2 f;
    asm("mov.b64 {%0, %1}, %2;" : "=f"(f.x), "=f"(f.y) : "l"(v));
    return f;
}

// ---------------- x transpose: (B,F) -> (F,B) ----------------------------
__global__ __launch_bounds__(256) void tt_transpose(const float* __restrict__ x,
                                                    float* __restrict__ xT) {
    __shared__ float tile[32][33];
    const int c0 = blockIdx.x * 32;
    const int r0 = blockIdx.y * 32;
    #pragma unroll
    for (int k = 0; k < 4; ++k) {
        int r = r0 + threadIdx.y + 8 * k;
        tile[threadIdx.y + 8 * k][threadIdx.x] = x[(size_t)r * FDIM + c0 + threadIdx.x];
    }
    __syncthreads();
    #pragma unroll
    for (int k = 0; k < 4; ++k) {
        int c = c0 + threadIdx.y + 8 * k;
        xT[(size_t)c * BDIM + r0 + threadIdx.x] = tile[threadIdx.x][threadIdx.y + 8 * k];
    }
}

// ---------------- Fourier feature builder (arg in [0,1)) ------------------
__device__ __forceinline__ void fourier9(float xv, float fmin, float* f) {
    float a = xv * fmin;
    float s1, c1;
    __sincosf(a, &s1, &c1);
    float s2 = s1 * c1 + c1 * s1, c2 = c1 * c1 - s1 * s1;
    float s3 = s2 * c1 + c2 * s1, c3 = c2 * c1 - s2 * s1;
    float s4 = s3 * c1 + c3 * s1, c4 = c3 * c1 - s3 * s1;
    f[0] = 1.f; f[1] = s1; f[2] = s2; f[3] = s3; f[4] = s4;
    f[5] = c1;  f[6] = c2; f[7] = c3; f[8] = c4;
}

// ---------------- level 0: d-split, R rows/thread --------------------------
// block 256 = 128 row-lanes x 2 d-halves. Covers 128*R rows per CTA.
template<int R>
__global__ __launch_bounds__(256, 2) void tt_level0(const float* __restrict__ xT,
                                                    const float* __restrict__ fminp,
                                                    const float* __restrict__ W0,
                                                    float* __restrict__ out) {
    __shared__ __align__(16) float sW[DIN0 * DIN0 * BOND];   // 5184 B
    __shared__ float sR[DIN0][128 * R];
    const int tid  = threadIdx.x;
    const int lane = tid & 127;
    const int half = tid >> 7;
    const int p    = blockIdx.x;

    {
        const float4* wg  = reinterpret_cast<const float4*>(W0 + (size_t)p * (DIN0 * DIN0 * BOND));
        float4*       ws4 = reinterpret_cast<float4*>(sW);
        for (int k = tid; k < (DIN0 * DIN0 * BOND) / 4; k += 256) ws4[k] = wg[k];
    }

    const int   bb   = blockIdx.y * (128 * R);
    const float fmin = *fminp;

    // cooperative sR fill: thread t handles rows t, t+256, ...
    for (int row = tid; row < 128 * R; row += 256) {
        float rr[DIN0];
        fourier9(xT[(size_t)(2 * p + 1) * BDIM + bb + row], fmin, rr);
        #pragma unroll
        for (int j = 0; j < DIN0; ++j) sR[j][row] = rr[j];
    }

    float l[R][DIN0];
    #pragma unroll
    for (int row = 0; row < R; ++row)
        fourier9(xT[(size_t)(2 * p) * BDIM + bb + lane + 128 * row], fmin, l[row]);
    __syncthreads();

    unsigned long long acc[R][4];
    #pragma unroll
    for (int row = 0; row < R; ++row)
        #pragma unroll
        for (int k = 0; k < 4; ++k) acc[row][k] = 0ull;

    #pragma unroll 3
    for (int j = 0; j < DIN0; ++j) {
        float rv[R];
        #pragma unroll
        for (int row = 0; row < R; ++row) rv[row] = sR[j][lane + 128 * row];
        #pragma unroll
        for (int i = 0; i < DIN0; ++i) {
            const ulonglong2* wv = reinterpret_cast<const ulonglong2*>(
                sW + (i * DIN0 + j) * BOND + half * 8);
            ulonglong2 wa = wv[0], wb = wv[1];
            #pragma unroll
            for (int row = 0; row < R; ++row) {
                float x = l[row][i] * rv[row];
                unsigned long long px = pack2(x, x);
                acc[row][0] = ffma2(px, wa.x, acc[row][0]);
                acc[row][1] = ffma2(px, wa.y, acc[row][1]);
                acc[row][2] = ffma2(px, wb.x, acc[row][2]);
                acc[row][3] = ffma2(px, wb.y, acc[row][3]);
            }
        }
    }

    #pragma unroll
    for (int row = 0; row < R; ++row) {
        int b = bb + lane + 128 * row;
        float4* op = reinterpret_cast<float4*>(out + ((size_t)p * BDIM + b) * BOND + half * 8);
        float2 u0 = unpack2(acc[row][0]), u1 = unpack2(acc[row][1]);
        float2 u2 = unpack2(acc[row][2]), u3 = unpack2(acc[row][3]);
        op[0] = make_float4(u0.x, u0.y, u1.x, u1.y);
        op[1] = make_float4(u2.x, u2.y, u3.x, u3.y);
    }
}

// ---------------- levels 1..6: d-split, R rows/thread ----------------------
template<int R>
__global__ __launch_bounds__(256, 2) void tt_level_mid(const float* __restrict__ in,
                                                       const float* __restrict__ W,
                                                       float* __restrict__ out) {
    __shared__ __align__(16) float sW[BOND * BOND * BOND];   // 16 KB
    __shared__ float sR[BOND][128 * R];
    const int tid  = threadIdx.x;
    const int lane = tid & 127;
    const int half = tid >> 7;
    const int p    = blockIdx.x;

    {
        const float4* wg  = reinterpret_cast<const float4*>(W + (size_t)p * (BOND * BOND * BOND));
        float4*       ws4 = reinterpret_cast<float4*>(sW);
        #pragma unroll
        for (int k = 0; k < 4; ++k) ws4[tid + 256 * k] = wg[tid + 256 * k];
    }

    const int bb = blockIdx.y * (128 * R);

    // cooperative sR fill (right operand)
    for (int row = tid; row < 128 * R; row += 256) {
        const float4* rp = reinterpret_cast<const float4*>(
            in + ((size_t)(2 * p + 1) * BDIM + bb + row) * BOND);
        #pragma unroll
        for (int k = 0; k < 4; ++k) {
            float4 u = rp[k];
            sR[4*k  ][row] = u.x;
            sR[4*k+1][row] = u.y;
            sR[4*k+2][row] = u.z;
            sR[4*k+3][row] = u.w;
        }
    }

    float l[R][BOND];
    #pragma unroll
    for (int row = 0; row < R; ++row) {
        const float4* lp = reinterpret_cast<const float4*>(
            in + ((size_t)(2 * p) * BDIM + bb + lane + 128 * row) * BOND);
        #pragma unroll
        for (int k = 0; k < 4; ++k) {
            float4 v = lp[k];
            l[row][4*k] = v.x; l[row][4*k+1] = v.y; l[row][4*k+2] = v.z; l[row][4*k+3] = v.w;
        }
    }
    __syncthreads();

    unsigned long long acc[R][4];
    #pragma unroll
    for (int row = 0; row < R; ++row)
        #pragma unroll
        for (int k = 0; k < 4; ++k) acc[row][k] = 0ull;

    #pragma unroll 4
    for (int j = 0; j < BOND; ++j) {
        float rv[R];
        #pragma unroll
        for (int row = 0; row < R; ++row) rv[row] = sR[j][lane + 128 * row];
        #pragma unroll
        for (int i = 0; i < BOND; ++i) {
            const ulonglong2* wv = reinterpret_cast<const ulonglong2*>(
                sW + (i * BOND + j) * BOND + half * 8);
            ulonglong2 wa = wv[0], wb = wv[1];
            #pragma unroll
            for (int row = 0; row < R; ++row) {
                float x = l[row][i] * rv[row];
                unsigned long long px = pack2(x, x);
                acc[row][0] = ffma2(px, wa.x, acc[row][0]);
                acc[row][1] = ffma2(px, wa.y, acc[row][1]);
                acc[row][2] = ffma2(px, wb.x, acc[row][2]);
                acc[row][3] = ffma2(px, wb.y, acc[row][3]);
            }
        }
    }

    #pragma unroll
    for (int row = 0; row < R; ++row) {
        int b = bb + lane + 128 * row;
        float4* op = reinterpret_cast<float4*>(out + ((size_t)p * BDIM + b) * BOND + half * 8);
        float2 u0 = unpack2(acc[row][0]), u1 = unpack2(acc[row][1]);
        float2 u2 = unpack2(acc[row][2]), u3 = unpack2(acc[row][3]);
        op[0] = make_float4(u0.x, u0.y, u1.x, u1.y);
        op[1] = make_float4(u2.x, u2.y, u3.x, u3.y);
    }
}

// ---------------- level 7: 16x16 -> scalar --------------------------------
__global__ __launch_bounds__(128) void tt_level7(const float* __restrict__ in,
                                                 const float* __restrict__ W,
                                                 float* __restrict__ out) {
    __shared__ float sW[BOND * BOND];
    const int tid = threadIdx.x;
    if (tid < BOND * BOND / 2) {
        reinterpret_cast<float2*>(sW)[tid] = reinterpret_cast<const float2*>(W)[tid];
    }
    __syncthreads();

    const int b = blockIdx.x * 128 + tid;
    float l[BOND], r[BOND];
    {
        const float4* lp = reinterpret_cast<const float4*>(in + ((size_t)0 * BDIM + b) * BOND);
        const float4* rp = reinterpret_cast<const float4*>(in + ((size_t)1 * BDIM + b) * BOND);
        #pragma unroll
        for (int k = 0; k < 4; ++k) {
            float4 v = lp[k]; l[4 * k] = v.x; l[4 * k + 1] = v.y; l[4 * k + 2] = v.z; l[4 * k + 3] = v.w;
            float4 u = rp[k]; r[4 * k] = u.x; r[4 * k + 1] = u.y; r[4 * k + 2] = u.z; r[4 * k + 3] = u.w;
        }
    }
    float acc = 0.f;
    #pragma unroll
    for (int i = 0; i < BOND; ++i) {
        float t = 0.f;
        #pragma unroll
        for (int j = 0; j < BOND; ++j) t = fmaf(sW[i * BOND + j], r[j], t);
        acc = fmaf(l[i], t, acc);
    }
    out[b] = acc;
}

// --------------------------------- launch ---------------------------------
extern "C" void kernel_launch(void* const* d_in, const int* in_sizes, int n_in,
                              void* d_out, int out_size) {
    const float* x    = (const float*)d_in[0];
    const float* fmin = (const float*)d_in[1];
    const float* W[8];
    for (int i = 0; i < 8; ++i) W[i] = (const float*)d_in[2 + i];

    float *xT, *bufA, *bufB;
    cudaGetSymbolAddress((void**)&xT,   g_xT);
    cudaGetSymbolAddress((void**)&bufA, g_bufA);
    cudaGetSymbolAddress((void**)&bufB, g_bufB);

    const int BT2 = BDIM / 256;   // 64 (R=2: 256 rows/CTA)
    const int BT1 = BDIM / 128;   // 128 (R=1: 128 rows/CTA)

    tt_transpose<<<dim3(FDIM / 32, BDIM / 32), dim3(32, 8)>>>(x, xT);
    tt_level0<2>   <<<dim3(128, BT2), 256>>>(xT, fmin, W[0], bufA);   // 8192 CTAs
    tt_level_mid<2><<<dim3(64, BT2), 256>>>(bufA, W[1], bufB);        // 4096
    tt_level_mid<2><<<dim3(32, BT2), 256>>>(bufB, W[2], bufA);        // 2048
    tt_level_mid<2><<<dim3(16, BT2), 256>>>(bufA, W[3], bufB);        // 1024
    tt_level_mid<2><<<dim3( 8, BT2), 256>>>(bufB, W[4], bufA);        //  512
    tt_level_mid<2><<<dim3( 4, BT2), 256>>>(bufA, W[5], bufB);        //  256
    tt_level_mid<1><<<dim3( 2, BT1), 256>>>(bufB, W[6], bufA);        //  256
    tt_level7      <<<BDIM / 128, 128>>>(bufA, W[7], (float*)d_out);
}